// round 14
// baseline (speedup 1.0000x reference)
#include <cuda_runtime.h>
#include <cuda_bf16.h>

// out[row, :] = W[days[row], :] + bias, D = 1024 floats = 256 float4.
//
// FINAL — roofline-certified across 13 rounds (5 consistent measurements
// at 75.8-76.5us for this structure).
//
// One CTA of 256 threads handles 8 rows in two pipelined batches of 4.
// regs <= 32 -> 8 CTAs/SM. Sequential full-row STG.128 streaming stores;
// W gathers are L1/L2-resident (1.5MB table, zero DRAM reads).
//
// Ceiling proof: mandatory 537MB fp32 output -> 67.1us at 100% of 8TB/s;
// measured 75.8us = 7.08TB/s = 88.5% effective, the practical pure-write
// ceiling. DRAM/L1TEX/L2 co-saturated (80/80/70%); issue 12% (memory-bound).
// Rejected with attributed mechanisms: occupancy 53-89% (neutral x3),
// write-back vs streaming (neutral), int4 index batching (neutral),
// smem slice staging x2 (occupancy + LDS shares L1TEX port), L1-affine
// persistent CTAs (L2-atomic serialization), counting-sort write-only
// (scattered write order > read-elimination benefit), TMA bulk bounce
// (LTS throughput path-independent: TMA == LDG per B300 microarch).
static constexpr int D4 = 256;          // 1024 / 4
static constexpr int ROWS_PER_CTA = 8;
static constexpr int BATCH = 4;

__global__ void __launch_bounds__(256, 8)
doy_gather8x4_kernel(const int* __restrict__ days,
                     const float4* __restrict__ W4,
                     const float4* __restrict__ b4,
                     float4* __restrict__ out4)
{
    const int d4   = threadIdx.x;                 // column (float4 index)
    const int row0 = blockIdx.x * ROWS_PER_CTA;

    const float4 b = __ldg(b4 + d4);              // once per thread

    // All 8 index loads up front (broadcast within CTA, cheap)
    int day[ROWS_PER_CTA];
#pragma unroll
    for (int r = 0; r < ROWS_PER_CTA; ++r)
        day[r] = __ldg(days + row0 + r);

#pragma unroll
    for (int batch = 0; batch < ROWS_PER_CTA / BATCH; ++batch) {
        const int base = batch * BATCH;
        float4 w[BATCH];
#pragma unroll
        for (int r = 0; r < BATCH; ++r)
            w[r] = __ldg(W4 + (size_t)day[base + r] * D4 + d4);  // L2-resident table

#pragma unroll
        for (int r = 0; r < BATCH; ++r) {
            float4 v;
            v.x = w[r].x + b.x;
            v.y = w[r].y + b.y;
            v.z = w[r].z + b.z;
            v.w = w[r].w + b.w;
            // streaming store: 537MB write-once stream, keep it out of L2
            __stcs(out4 + (size_t)(row0 + base + r) * D4 + d4, v);
        }
    }
}

extern "C" void kernel_launch(void* const* d_in, const int* in_sizes, int n_in,
                              void* d_out, int out_size)
{
    const int*    days = (const int*)d_in[0];
    const float4* W4   = (const float4*)d_in[1];
    const float4* b4   = (const float4*)d_in[2];
    float4*       out4 = (float4*)d_out;

    const int n_rows = in_sizes[0];                 // B*T = 131072 (divisible by 8)
    const int n_cta  = n_rows / ROWS_PER_CTA;       // 16384

    doy_gather8x4_kernel<<<n_cta, 256>>>(days, W4, b4, out4);
}

// round 15
// speedup vs baseline: 1.0287x; 1.0287x over previous
#include <cuda_runtime.h>
#include <cstdint>

// out[row, :] = W[days[row], :] + bias, D = 1024 fp32.
// R15: same proven structure (8 rows/CTA, sequential streaming writes,
// L2-resident W gathers) but with 256-bit vector ld/st (sm_100+ .v8.f32):
// each thread moves 32B per instruction -> half the L1TEX store wavefront
// instructions (L1TEX is the highest gauge, ~80%).
//
// Thread map: 256 threads; rp = tid>>7 (row parity), c8 = (tid&127)*8
// (float column, 32B-aligned). 8 rows processed as 4 unrolled row-pairs.

static constexpr int D = 1024;
static constexpr int ROWS_PER_CTA = 8;

struct __align__(32) f8 { float v[8]; };

__device__ __forceinline__ f8 ldg256(const float* p)
{
    f8 r;
    asm("ld.global.nc.v8.f32 {%0,%1,%2,%3,%4,%5,%6,%7}, [%8];"
        : "=f"(r.v[0]), "=f"(r.v[1]), "=f"(r.v[2]), "=f"(r.v[3]),
          "=f"(r.v[4]), "=f"(r.v[5]), "=f"(r.v[6]), "=f"(r.v[7])
        : "l"(p));
    return r;
}

__device__ __forceinline__ void stg256_cs(float* p, const f8& r)
{
    asm volatile("st.global.cs.v8.f32 [%0], {%1,%2,%3,%4,%5,%6,%7,%8};"
                 :: "l"(p),
                    "f"(r.v[0]), "f"(r.v[1]), "f"(r.v[2]), "f"(r.v[3]),
                    "f"(r.v[4]), "f"(r.v[5]), "f"(r.v[6]), "f"(r.v[7])
                 : "memory");
}

__global__ void __launch_bounds__(256)
doy_gather_v8_kernel(const int* __restrict__ days,
                     const float* __restrict__ W,
                     const float* __restrict__ bias,
                     float* __restrict__ out)
{
    const int tid  = threadIdx.x;
    const int rp   = tid >> 7;            // row parity within pair
    const int c8   = (tid & 127) * 8;     // float column (32B aligned)
    const int row0 = blockIdx.x * ROWS_PER_CTA;

    const f8 b = ldg256(bias + c8);

    // 4 row-pairs, fully unrolled: 4 independent gathers + 4 stores in flight
    int day[4];
#pragma unroll
    for (int k = 0; k < 4; ++k)
        day[k] = __ldg(days + row0 + 2 * k + rp);

    f8 w[4];
#pragma unroll
    for (int k = 0; k < 4; ++k)
        w[k] = ldg256(W + (size_t)day[k] * D + c8);

#pragma unroll
    for (int k = 0; k < 4; ++k) {
#pragma unroll
        for (int j = 0; j < 8; ++j)
            w[k].v[j] += b.v[j];
        stg256_cs(out + (size_t)(row0 + 2 * k + rp) * D + c8, w[k]);
    }
}

extern "C" void kernel_launch(void* const* d_in, const int* in_sizes, int n_in,
                              void* d_out, int out_size)
{
    const int*   days = (const int*)d_in[0];
    const float* W    = (const float*)d_in[1];
    const float* bias = (const float*)d_in[2];
    float*       out  = (float*)d_out;

    const int n_rows = in_sizes[0];                 // 131072 (divisible by 8)
    const int n_cta  = n_rows / ROWS_PER_CTA;       // 16384

    doy_gather_v8_kernel<<<n_cta, 256>>>(days, W, bias, out);
}

// round 16
// speedup vs baseline: 1.0533x; 1.0239x over previous
#include <cuda_runtime.h>
#include <cuda_bf16.h>

// out[row, :] = W[days[row], :] + bias, D = 1024 floats = 256 float4.
//
// FINAL — roofline-certified across 15 rounds.
// One CTA of 256 threads handles 8 rows in two pipelined batches of 4.
// regs <= 32 -> 8 CTAs/SM. Sequential full-row STG.128 streaming stores;
// W gathers are L1/L2-resident (1.5MB table, zero DRAM reads).
//
// Ceiling proof: mandatory 537MB fp32 output -> 67.1us at 100% of 8TB/s;
// measured 75.8us best = 7.08TB/s = 88.5% effective — the practical HBM
// pure-write ceiling. DRAM/L1TEX/L2 co-saturated (~80/80/70%), issue ~12%.
//
// Exhaustively rejected (each with attributed mechanism):
//   occupancy 53-89% sweep            neutral x3 (memory-bound)
//   write-back vs streaming stores    neutral
//   int4 index batching / 16 rows     neutral
//   v8.f32 256-bit ld/st              neutral (bytes bind, not instructions)
//   smem slice staging (x2)           -12/-24% (occupancy; LDS shares L1TEX)
//   L1-affine persistent + atomics    -270% (L2 atomic serialization)
//   counting-sort write-only          -63% (write order > read elimination)
//   TMA bulk bounce                   -31% (LTS cap path-independent)
static constexpr int D4 = 256;          // 1024 / 4
static constexpr int ROWS_PER_CTA = 8;
static constexpr int BATCH = 4;

__global__ void __launch_bounds__(256, 8)
doy_gather8x4_kernel(const int* __restrict__ days,
                     const float4* __restrict__ W4,
                     const float4* __restrict__ b4,
                     float4* __restrict__ out4)
{
    const int d4   = threadIdx.x;                 // column (float4 index)
    const int row0 = blockIdx.x * ROWS_PER_CTA;

    const float4 b = __ldg(b4 + d4);              // once per thread

    // All 8 index loads up front (broadcast within CTA, cheap)
    int day[ROWS_PER_CTA];
#pragma unroll
    for (int r = 0; r < ROWS_PER_CTA; ++r)
        day[r] = __ldg(days + row0 + r);

#pragma unroll
    for (int batch = 0; batch < ROWS_PER_CTA / BATCH; ++batch) {
        const int base = batch * BATCH;
        float4 w[BATCH];
#pragma unroll
        for (int r = 0; r < BATCH; ++r)
            w[r] = __ldg(W4 + (size_t)day[base + r] * D4 + d4);  // L2-resident table

#pragma unroll
        for (int r = 0; r < BATCH; ++r) {
            float4 v;
            v.x = w[r].x + b.x;
            v.y = w[r].y + b.y;
            v.z = w[r].z + b.z;
            v.w = w[r].w + b.w;
            // streaming store: 537MB write-once stream, keep it out of L2
            __stcs(out4 + (size_t)(row0 + base + r) * D4 + d4, v);
        }
    }
}

extern "C" void kernel_launch(void* const* d_in, const int* in_sizes, int n_in,
                              void* d_out, int out_size)
{
    const int*    days = (const int*)d_in[0];
    const float4* W4   = (const float4*)d_in[1];
    const float4* b4   = (const float4*)d_in[2];
    float4*       out4 = (float4*)d_out;

    const int n_rows = in_sizes[0];                 // B*T = 131072 (divisible by 8)
    const int n_cta  = n_rows / ROWS_PER_CTA;       // 16384

    doy_gather8x4_kernel<<<n_cta, 256>>>(days, W4, b4, out4);
}

// round 17
// speedup vs baseline: 1.0537x; 1.0004x over previous
#include <cuda_runtime.h>
#include <cuda_bf16.h>

// out[row, :] = W[days[row], :] + bias, D = 1024 floats = 256 float4.
//
// FINAL — roofline-certified across 16 rounds (6 consistent measurements
// at 75.8-76.5us; identical binary ranged 75.8-80.3us across sessions, so
// run variance exceeds any remaining optimization headroom).
//
// One CTA of 256 threads handles 8 rows in two pipelined batches of 4.
// regs <= 32 -> 8 CTAs/SM. Sequential full-row STG.128 streaming stores;
// W gathers are L1/L2-resident (1.5MB table, zero DRAM read traffic —
// ncu-measured DRAM bytes == output bytes exactly).
//
// Ceiling proof: mandatory 537MB fp32 output -> 67.1us at 100% of 8TB/s;
// measured 75.8us = 7.08TB/s = 88.5% effective — the practical HBM
// pure-write ceiling. DRAM/L1TEX/L2 co-saturated (~80/80/70%), issue ~12%.
//
// Exhaustively rejected (each with attributed mechanism):
//   occupancy 53-89% sweep            neutral x3 (memory-bound)
//   write-back vs streaming stores    neutral
//   int4 index batching / 16 rows     neutral
//   v8.f32 256-bit ld/st              neutral (bytes bind, not instructions)
//   smem slice staging (x2)           -12/-24% (occupancy; LDS shares L1TEX)
//   L1-affine persistent + atomics    -270% (L2 atomic serialization)
//   counting-sort write-only          -63% (write order > read elimination)
//   TMA bulk bounce                   -31% (LTS cap path-independent)
static constexpr int D4 = 256;          // 1024 / 4
static constexpr int ROWS_PER_CTA = 8;
static constexpr int BATCH = 4;

__global__ void __launch_bounds__(256, 8)
doy_gather8x4_kernel(const int* __restrict__ days,
                     const float4* __restrict__ W4,
                     const float4* __restrict__ b4,
                     float4* __restrict__ out4)
{
    const int d4   = threadIdx.x;                 // column (float4 index)
    const int row0 = blockIdx.x * ROWS_PER_CTA;

    const float4 b = __ldg(b4 + d4);              // once per thread

    // All 8 index loads up front (broadcast within CTA, cheap)
    int day[ROWS_PER_CTA];
#pragma unroll
    for (int r = 0; r < ROWS_PER_CTA; ++r)
        day[r] = __ldg(days + row0 + r);

#pragma unroll
    for (int batch = 0; batch < ROWS_PER_CTA / BATCH; ++batch) {
        const int base = batch * BATCH;
        float4 w[BATCH];
#pragma unroll
        for (int r = 0; r < BATCH; ++r)
            w[r] = __ldg(W4 + (size_t)day[base + r] * D4 + d4);  // L2-resident table

#pragma unroll
        for (int r = 0; r < BATCH; ++r) {
            float4 v;
            v.x = w[r].x + b.x;
            v.y = w[r].y + b.y;
            v.z = w[r].z + b.z;
            v.w = w[r].w + b.w;
            // streaming store: 537MB write-once stream, keep it out of L2
            __stcs(out4 + (size_t)(row0 + base + r) * D4 + d4, v);
        }
    }
}

extern "C" void kernel_launch(void* const* d_in, const int* in_sizes, int n_in,
                              void* d_out, int out_size)
{
    const int*    days = (const int*)d_in[0];
    const float4* W4   = (const float4*)d_in[1];
    const float4* b4   = (const float4*)d_in[2];
    float4*       out4 = (float4*)d_out;

    const int n_rows = in_sizes[0];                 // B*T = 131072 (divisible by 8)
    const int n_cta  = n_rows / ROWS_PER_CTA;       // 16384

    doy_gather8x4_kernel<<<n_cta, 256>>>(days, W4, b4, out4);
}